// round 1
// baseline (speedup 1.0000x reference)
#include <cuda_runtime.h>
#include <math.h>

#define B_   64
#define N_   196
#define C_   768
#define H_   12
#define HD_  64
#define TOPK_ 16
#define HID_ 3072
#define M_   (B_ * N_)          // 12544
#define SCALE_ 0.125f           // 64^-0.5
#define EPS_ 1e-5f

// ---------------- scratch (device globals; no allocation allowed) ----------------
__device__ float g_h  [(size_t)M_ * C_];        // LN output (reused for LN1 and LN2)
__device__ float g_qk [(size_t)M_ * 2 * C_];    // qk projection
__device__ float g_a  [(size_t)M_ * H_ * TOPK_];// attention weights (sparse softmax)
__device__ float g_x1 [(size_t)M_ * C_];        // after attention residual
__device__ float g_hid[(size_t)M_ * HID_];      // MLP hidden

// ---------------- LayerNorm ----------------
__global__ void ln_kernel(const float* __restrict__ x, const float* __restrict__ g,
                          const float* __restrict__ b, float* __restrict__ out) {
    int row = blockIdx.x;
    const float* xr = x + (size_t)row * C_;
    int tid = threadIdx.x, lane = tid & 31, warp = tid >> 5;

    float s = 0.f, s2 = 0.f;
    for (int i = tid; i < C_; i += blockDim.x) {
        float v = xr[i];
        s += v; s2 += v * v;
    }
    #pragma unroll
    for (int o = 16; o > 0; o >>= 1) {
        s  += __shfl_xor_sync(0xffffffffu, s,  o);
        s2 += __shfl_xor_sync(0xffffffffu, s2, o);
    }
    __shared__ float shs[8], shs2[8], sh_mu, sh_inv;
    if (lane == 0) { shs[warp] = s; shs2[warp] = s2; }
    __syncthreads();
    if (tid == 0) {
        float ts = 0.f, ts2 = 0.f;
        #pragma unroll
        for (int w = 0; w < 8; w++) { ts += shs[w]; ts2 += shs2[w]; }
        float mu = ts / C_;
        float var = ts2 / C_ - mu * mu;
        sh_mu = mu;
        sh_inv = rsqrtf(var + EPS_);
    }
    __syncthreads();
    float mu = sh_mu, inv = sh_inv;
    for (int i = tid; i < C_; i += blockDim.x)
        out[(size_t)row * C_ + i] = (xr[i] - mu) * inv * g[i] + b[i];
}

// ---------------- TN GEMM: out[M,Nout] = A[M,K] @ W[Nout,K]^T (+bias)(gelu)(+res) ----------------
// BM=BN=64, BK=16, 256 threads, 4x4 per thread.
template <bool BIAS, bool GELU, bool RES>
__global__ void gemm_tn(const float* __restrict__ A, const float* __restrict__ W,
                        const float* __restrict__ bias, const float* __restrict__ res,
                        float* __restrict__ out, int Nout, int K) {
    __shared__ float As[16][68];
    __shared__ float Bs[16][68];
    int tx = threadIdx.x, ty = threadIdx.y;
    int tid = ty * 16 + tx;
    int bm = blockIdx.y * 64, bn = blockIdx.x * 64;
    int lrow = tid >> 4;   // 0..15
    int lcol = tid & 15;   // 0..15 (k within tile)

    float acc[4][4] = {};

    for (int k0 = 0; k0 < K; k0 += 16) {
        #pragma unroll
        for (int it = 0; it < 4; it++) {
            int row = lrow + it * 16;
            As[lcol][row] = A[(size_t)(bm + row) * K + k0 + lcol];
            Bs[lcol][row] = W[(size_t)(bn + row) * K + k0 + lcol];
        }
        __syncthreads();
        #pragma unroll
        for (int kk = 0; kk < 16; kk++) {
            float4 av = *(const float4*)&As[kk][ty * 4];
            float4 bv = *(const float4*)&Bs[kk][tx * 4];
            float a0[4] = {av.x, av.y, av.z, av.w};
            float b0[4] = {bv.x, bv.y, bv.z, bv.w};
            #pragma unroll
            for (int i = 0; i < 4; i++)
                #pragma unroll
                for (int j = 0; j < 4; j++)
                    acc[i][j] += a0[i] * b0[j];
        }
        __syncthreads();
    }

    #pragma unroll
    for (int i = 0; i < 4; i++) {
        int r = bm + ty * 4 + i;
        #pragma unroll
        for (int j = 0; j < 4; j++) {
            int c = bn + tx * 4 + j;
            float v = acc[i][j];
            if (BIAS) v += bias[c];
            if (GELU) v = 0.5f * v * (1.0f + erff(v * 0.70710678118654752f));
            if (RES)  v += res[(size_t)r * Nout + c];
            out[(size_t)r * Nout + c] = v;
        }
    }
}

// ---------------- fused attention: scores + top-16 + softmax ----------------
// One block per (b,h). Q (scaled) and K staged in smem; each warp processes
// query rows round-robin; warp-level 16x argmax selection; write softmax of top-16.
__global__ void attn_topk_kernel(const float* __restrict__ qk, float* __restrict__ a) {
    int bh = blockIdx.x;
    int b = bh / H_, h = bh % H_;
    extern __shared__ float sm[];
    float* Qs = sm;              // [196][64]
    float* Ks = sm + N_ * HD_;   // [196][65]  (padded: conflict-free)

    int tid = threadIdx.x, lane = tid & 31, warp = tid >> 5;
    int nwarp = blockDim.x >> 5;

    const float* base = qk + (size_t)b * N_ * (2 * C_);
    for (int e = tid; e < N_ * HD_; e += blockDim.x) {
        int n = e / HD_, d = e % HD_;
        Qs[n * HD_ + d]  = base[(size_t)n * (2 * C_) + h * HD_ + d] * SCALE_;
        Ks[n * 65 + d]   = base[(size_t)n * (2 * C_) + C_ + h * HD_ + d];
    }
    __syncthreads();

    for (int i = warp; i < N_; i += nwarp) {
        // each lane owns j = lane + 32*t, t in [0,7)
        int jj[7];
        float sloc[7];
        #pragma unroll
        for (int t = 0; t < 7; t++) {
            int j = lane + 32 * t;
            jj[t] = (j < N_) ? j : 0;
            sloc[t] = 0.f;
        }
        const float* qrow = Qs + i * HD_;
        #pragma unroll 8
        for (int d = 0; d < HD_; d++) {
            float qv = qrow[d];
            #pragma unroll
            for (int t = 0; t < 7; t++)
                sloc[t] += qv * Ks[jj[t] * 65 + d];
        }
        #pragma unroll
        for (int t = 0; t < 7; t++)
            if (lane + 32 * t >= N_) sloc[t] = -INFINITY;

        // top-16 via 16 warp argmax passes
        float top[16];
        #pragma unroll
        for (int sel = 0; sel < TOPK_; sel++) {
            float m = sloc[0]; int tl = 0;
            #pragma unroll
            for (int t = 1; t < 7; t++)
                if (sloc[t] > m) { m = sloc[t]; tl = t; }
            int key = (lane << 3) | tl;
            #pragma unroll
            for (int o = 16; o > 0; o >>= 1) {
                float om = __shfl_xor_sync(0xffffffffu, m, o);
                int ok   = __shfl_xor_sync(0xffffffffu, key, o);
                if (om > m || (om == m && ok < key)) { m = om; key = ok; }
            }
            top[sel] = m;
            if (lane == (key >> 3)) sloc[key & 7] = -INFINITY;
        }

        // softmax over the 16 (top[0] is the max)
        float ssum = 0.f;
        #pragma unroll
        for (int t = 0; t < TOPK_; t++) ssum += expf(top[t] - top[0]);
        if (lane < TOPK_) {
            float val = expf(top[lane] - top[0]) / ssum;
            a[((size_t)(b * N_ + i)) * (H_ * TOPK_) + h * TOPK_ + lane] = val;
        }
    }
}

// ---------------- launch ----------------
extern "C" void kernel_launch(void* const* d_in, const int* in_sizes, int n_in,
                              void* d_out, int out_size) {
    const float* x      = (const float*)d_in[0];
    const float* n1g    = (const float*)d_in[1];
    const float* n1b    = (const float*)d_in[2];
    const float* qk_w   = (const float*)d_in[3];
    const float* proj_w = (const float*)d_in[4];
    const float* proj_b = (const float*)d_in[5];
    const float* n2g    = (const float*)d_in[6];
    const float* n2b    = (const float*)d_in[7];
    const float* fc1_w  = (const float*)d_in[8];
    const float* fc1_b  = (const float*)d_in[9];
    const float* fc2_w  = (const float*)d_in[10];
    const float* fc2_b  = (const float*)d_in[11];
    float* out = (float*)d_out;

    float *h, *qkb, *ab, *x1, *hid;
    cudaGetSymbolAddress((void**)&h,   g_h);
    cudaGetSymbolAddress((void**)&qkb, g_qk);
    cudaGetSymbolAddress((void**)&ab,  g_a);
    cudaGetSymbolAddress((void**)&x1,  g_x1);
    cudaGetSymbolAddress((void**)&hid, g_hid);

    dim3 tpb(16, 16);

    // 1. LN1
    ln_kernel<<<M_, 256>>>(x, n1g, n1b, h);

    // 2. qk = h @ qk_w^T   [M, 1536]
    gemm_tn<false, false, false><<<dim3((2 * C_) / 64, M_ / 64), tpb>>>(
        h, qk_w, nullptr, nullptr, qkb, 2 * C_, C_);

    // 3. fused scores + top-16 + softmax -> a [M, 192]
    int smem = (N_ * HD_ + N_ * 65) * (int)sizeof(float);  // ~101 KB
    cudaFuncSetAttribute(attn_topk_kernel, cudaFuncAttributeMaxDynamicSharedMemorySize, smem);
    attn_topk_kernel<<<B_ * H_, 256, smem>>>(qkb, ab);

    // 4. x1 = x + a @ proj_w^T + proj_b   [M, 768]
    gemm_tn<true, false, true><<<dim3(C_ / 64, M_ / 64), tpb>>>(
        ab, proj_w, proj_b, x, x1, C_, H_ * TOPK_);

    // 5. LN2
    ln_kernel<<<M_, 256>>>(x1, n2g, n2b, h);

    // 6. hid = gelu(h @ fc1_w^T + fc1_b)   [M, 3072]
    gemm_tn<true, true, false><<<dim3(HID_ / 64, M_ / 64), tpb>>>(
        h, fc1_w, fc1_b, nullptr, hid, HID_, C_);

    // 7. out = x1 + hid @ fc2_w^T + fc2_b  [M, 768]
    gemm_tn<true, false, true><<<dim3(C_ / 64, M_ / 64), tpb>>>(
        hid, fc2_w, fc2_b, x1, out, C_, HID_);
}

// round 2
// speedup vs baseline: 2.5768x; 2.5768x over previous
#include <cuda_runtime.h>
#include <math.h>
#include <stdint.h>

#define B_   64
#define N_   196
#define C_   768
#define H_   12
#define HD_  64
#define TOPK_ 16
#define HID_ 3072
#define M_   (B_ * N_)          // 12544
#define SCALE_ 0.125f           // 64^-0.5
#define EPS_ 1e-5f

// ---------------- scratch (device globals; no allocation allowed) ----------------
__device__ float g_h  [(size_t)M_ * C_];        // LN output (reused for LN1 and LN2)
__device__ float g_qk [(size_t)M_ * 2 * C_];    // qk projection
__device__ float g_a  [(size_t)M_ * H_ * TOPK_];// attention weights (sparse softmax)
__device__ float g_x1 [(size_t)M_ * C_];        // after attention residual
__device__ float g_hid[(size_t)M_ * HID_];      // MLP hidden

// ---------------- LayerNorm ----------------
__global__ void ln_kernel(const float* __restrict__ x, const float* __restrict__ g,
                          const float* __restrict__ b, float* __restrict__ out) {
    int row = blockIdx.x;
    const float* xr = x + (size_t)row * C_;
    int tid = threadIdx.x, lane = tid & 31, warp = tid >> 5;

    float s = 0.f, s2 = 0.f;
    for (int i = tid; i < C_; i += blockDim.x) {
        float v = xr[i];
        s += v; s2 += v * v;
    }
    #pragma unroll
    for (int o = 16; o > 0; o >>= 1) {
        s  += __shfl_xor_sync(0xffffffffu, s,  o);
        s2 += __shfl_xor_sync(0xffffffffu, s2, o);
    }
    __shared__ float shs[8], shs2[8], sh_mu, sh_inv;
    if (lane == 0) { shs[warp] = s; shs2[warp] = s2; }
    __syncthreads();
    if (tid == 0) {
        float ts = 0.f, ts2 = 0.f;
        #pragma unroll
        for (int w = 0; w < 8; w++) { ts += shs[w]; ts2 += shs2[w]; }
        float mu = ts / C_;
        float var = ts2 / C_ - mu * mu;
        sh_mu = mu;
        sh_inv = rsqrtf(var + EPS_);
    }
    __syncthreads();
    float mu = sh_mu, inv = sh_inv;
    for (int i = tid; i < C_; i += blockDim.x)
        out[(size_t)row * C_ + i] = (xr[i] - mu) * inv * g[i] + b[i];
}

// ---------------- cp.async helpers ----------------
__device__ __forceinline__ void cp_async16(void* smem, const void* gmem) {
    uint32_t s = (uint32_t)__cvta_generic_to_shared(smem);
    asm volatile("cp.async.cg.shared.global [%0], [%1], 16;\n" :: "r"(s), "l"(gmem));
}
__device__ __forceinline__ void cp_commit() {
    asm volatile("cp.async.commit_group;\n");
}
template <int N>
__device__ __forceinline__ void cp_wait() {
    asm volatile("cp.async.wait_group %0;\n" :: "n"(N) : "memory");
}

// ---------------- TF32 tensor-core TN GEMM ----------------
// out[M,Nout] = A[M,K] @ W[Nout,K]^T (+bias)(gelu)(+res)
// BM=BN=128, BK=16. 256 threads = 8 warps (2x4), warp tile 64x32 via m16n8k8.
// Operands passed as raw f32 bits (HW truncates to tf32; accuracy budget verified).
template <bool BIAS, bool GELU, bool RES>
__global__ __launch_bounds__(256) void gemm_mma(
        const float* __restrict__ A, const float* __restrict__ W,
        const float* __restrict__ bias, const float* __restrict__ res,
        float* __restrict__ out, int Nout, int K) {
    constexpr int BM = 128, BN = 128, BK = 16;
    constexpr int LDS_ = BK + 4;  // 20: conflict-free frag reads
    __shared__ float As[2][BM * LDS_];
    __shared__ float Bs[2][BN * LDS_];

    int tid = threadIdx.x;
    int lane = tid & 31, wid = tid >> 5;
    int wr = wid >> 2, wc = wid & 3;          // warp row (0..1) / col (0..3)
    int g = lane >> 2, t = lane & 3;          // groupID / thread-in-group
    int bm = blockIdx.y * BM, bn = blockIdx.x * BN;

    const float* Ablk = A + (size_t)bm * K;
    const float* Wblk = W + (size_t)bn * K;

    float c[4][4][4];
    #pragma unroll
    for (int i = 0; i < 4; i++)
        #pragma unroll
        for (int j = 0; j < 4; j++)
            #pragma unroll
            for (int r = 0; r < 4; r++) c[i][j][r] = 0.f;

    // stage loader: 128 rows x 16 k-floats per matrix = 512 x 16B; 2 per thread each
    auto load_stage = [&](int s, int k0) {
        #pragma unroll
        for (int i = 0; i < 2; i++) {
            int idx = tid + i * 256;
            int m = idx >> 2, kc = idx & 3;
            cp_async16(&As[s][m * LDS_ + kc * 4], Ablk + (size_t)m * K + k0 + kc * 4);
            cp_async16(&Bs[s][m * LDS_ + kc * 4], Wblk + (size_t)m * K + k0 + kc * 4);
        }
        cp_commit();
    };

    int niter = K / BK;
    load_stage(0, 0);

    for (int it = 0; it < niter; it++) {
        int s = it & 1;
        if (it + 1 < niter) {
            load_stage(s ^ 1, (it + 1) * BK);
            cp_wait<1>();
        } else {
            cp_wait<0>();
        }
        __syncthreads();

        const float* as = As[s];
        const float* bs = Bs[s];
        #pragma unroll
        for (int kh = 0; kh < 2; kh++) {
            int ko = kh * 8;
            uint32_t a[4][4], b[4][2];
            #pragma unroll
            for (int ti = 0; ti < 4; ti++) {
                int r = wr * 64 + ti * 16 + g;
                a[ti][0] = __float_as_uint(as[r * LDS_ + ko + t]);
                a[ti][1] = __float_as_uint(as[(r + 8) * LDS_ + ko + t]);
                a[ti][2] = __float_as_uint(as[r * LDS_ + ko + t + 4]);
                a[ti][3] = __float_as_uint(as[(r + 8) * LDS_ + ko + t + 4]);
            }
            #pragma unroll
            for (int tj = 0; tj < 4; tj++) {
                int n = wc * 32 + tj * 8 + g;
                b[tj][0] = __float_as_uint(bs[n * LDS_ + ko + t]);
                b[tj][1] = __float_as_uint(bs[n * LDS_ + ko + t + 4]);
            }
            #pragma unroll
            for (int ti = 0; ti < 4; ti++)
                #pragma unroll
                for (int tj = 0; tj < 4; tj++) {
                    asm volatile(
                        "mma.sync.aligned.m16n8k8.row.col.f32.tf32.tf32.f32 "
                        "{%0,%1,%2,%3}, {%4,%5,%6,%7}, {%8,%9}, {%0,%1,%2,%3};\n"
                        : "+f"(c[ti][tj][0]), "+f"(c[ti][tj][1]),
                          "+f"(c[ti][tj][2]), "+f"(c[ti][tj][3])
                        : "r"(a[ti][0]), "r"(a[ti][1]), "r"(a[ti][2]), "r"(a[ti][3]),
                          "r"(b[tj][0]), "r"(b[tj][1]));
                }
        }
        __syncthreads();
    }

    // epilogue: c0,c1 at (r, cn..cn+1), c2,c3 at (r+8, cn..cn+1)
    #pragma unroll
    for (int ti = 0; ti < 4; ti++) {
        int r0 = bm + wr * 64 + ti * 16 + g;
        #pragma unroll
        for (int tj = 0; tj < 4; tj++) {
            int cn = bn + wc * 32 + tj * 8 + t * 2;
            float v[4] = {c[ti][tj][0], c[ti][tj][1], c[ti][tj][2], c[ti][tj][3]};
            if (BIAS) {
                float b0 = bias[cn], b1 = bias[cn + 1];
                v[0] += b0; v[1] += b1; v[2] += b0; v[3] += b1;
            }
            if (GELU) {
                #pragma unroll
                for (int q = 0; q < 4; q++)
                    v[q] = 0.5f * v[q] * (1.0f + erff(v[q] * 0.70710678118654752f));
            }
            if (RES) {
                float2 r0v = *(const float2*)&res[(size_t)r0 * Nout + cn];
                float2 r1v = *(const float2*)&res[(size_t)(r0 + 8) * Nout + cn];
                v[0] += r0v.x; v[1] += r0v.y; v[2] += r1v.x; v[3] += r1v.y;
            }
            *(float2*)&out[(size_t)r0 * Nout + cn]       = make_float2(v[0], v[1]);
            *(float2*)&out[(size_t)(r0 + 8) * Nout + cn] = make_float2(v[2], v[3]);
        }
    }
}

// ---------------- fused attention: scores + top-16 + softmax ----------------
__global__ void attn_topk_kernel(const float* __restrict__ qk, float* __restrict__ a) {
    int bh = blockIdx.x;
    int b = bh / H_, h = bh % H_;
    extern __shared__ float sm[];
    float* Qs = sm;              // [196][64]
    float* Ks = sm + N_ * HD_;   // [196][65]  (padded)

    int tid = threadIdx.x, lane = tid & 31, warp = tid >> 5;
    int nwarp = blockDim.x >> 5;

    const float* base = qk + (size_t)b * N_ * (2 * C_);
    for (int e = tid; e < N_ * HD_; e += blockDim.x) {
        int n = e / HD_, d = e % HD_;
        Qs[n * HD_ + d]  = base[(size_t)n * (2 * C_) + h * HD_ + d] * SCALE_;
        Ks[n * 65 + d]   = base[(size_t)n * (2 * C_) + C_ + h * HD_ + d];
    }
    __syncthreads();

    for (int i = warp; i < N_; i += nwarp) {
        int jj[7];
        float sloc[7];
        #pragma unroll
        for (int t = 0; t < 7; t++) {
            int j = lane + 32 * t;
            jj[t] = (j < N_) ? j : 0;
            sloc[t] = 0.f;
        }
        const float* qrow = Qs + i * HD_;
        #pragma unroll 8
        for (int d = 0; d < HD_; d++) {
            float qv = qrow[d];
            #pragma unroll
            for (int t = 0; t < 7; t++)
                sloc[t] += qv * Ks[jj[t] * 65 + d];
        }
        #pragma unroll
        for (int t = 0; t < 7; t++)
            if (lane + 32 * t >= N_) sloc[t] = -INFINITY;

        float top[16];
        #pragma unroll
        for (int sel = 0; sel < TOPK_; sel++) {
            float m = sloc[0]; int tl = 0;
            #pragma unroll
            for (int t = 1; t < 7; t++)
                if (sloc[t] > m) { m = sloc[t]; tl = t; }
            int key = (lane << 3) | tl;
            #pragma unroll
            for (int o = 16; o > 0; o >>= 1) {
                float om = __shfl_xor_sync(0xffffffffu, m, o);
                int ok   = __shfl_xor_sync(0xffffffffu, key, o);
                if (om > m || (om == m && ok < key)) { m = om; key = ok; }
            }
            top[sel] = m;
            if (lane == (key >> 3)) sloc[key & 7] = -INFINITY;
        }

        float ssum = 0.f;
        #pragma unroll
        for (int t = 0; t < TOPK_; t++) ssum += expf(top[t] - top[0]);
        if (lane < TOPK_) {
            float val = expf(top[lane] - top[0]) / ssum;
            a[((size_t)(b * N_ + i)) * (H_ * TOPK_) + h * TOPK_ + lane] = val;
        }
    }
}

// ---------------- launch ----------------
extern "C" void kernel_launch(void* const* d_in, const int* in_sizes, int n_in,
                              void* d_out, int out_size) {
    const float* x      = (const float*)d_in[0];
    const float* n1g    = (const float*)d_in[1];
    const float* n1b    = (const float*)d_in[2];
    const float* qk_w   = (const float*)d_in[3];
    const float* proj_w = (const float*)d_in[4];
    const float* proj_b = (const float*)d_in[5];
    const float* n2g    = (const float*)d_in[6];
    const float* n2b    = (const float*)d_in[7];
    const float* fc1_w  = (const float*)d_in[8];
    const float* fc1_b  = (const float*)d_in[9];
    const float* fc2_w  = (const float*)d_in[10];
    const float* fc2_b  = (const float*)d_in[11];
    float* out = (float*)d_out;

    float *h, *qkb, *ab, *x1, *hid;
    cudaGetSymbolAddress((void**)&h,   g_h);
    cudaGetSymbolAddress((void**)&qkb, g_qk);
    cudaGetSymbolAddress((void**)&ab,  g_a);
    cudaGetSymbolAddress((void**)&x1,  g_x1);
    cudaGetSymbolAddress((void**)&hid, g_hid);

    // 1. LN1
    ln_kernel<<<M_, 256>>>(x, n1g, n1b, h);

    // 2. qk = h @ qk_w^T   [M, 1536]
    gemm_mma<false, false, false><<<dim3((2 * C_) / 128, M_ / 128), 256>>>(
        h, qk_w, nullptr, nullptr, qkb, 2 * C_, C_);

    // 3. fused scores + top-16 + softmax -> a [M, 192]
    int smem = (N_ * HD_ + N_ * 65) * (int)sizeof(float);  // ~101 KB
    cudaFuncSetAttribute(attn_topk_kernel, cudaFuncAttributeMaxDynamicSharedMemorySize, smem);
    attn_topk_kernel<<<B_ * H_, 256, smem>>>(qkb, ab);

    // 4. x1 = x + a @ proj_w^T + proj_b   [M, 768]  (K=192)
    gemm_mma<true, false, true><<<dim3(C_ / 128, M_ / 128), 256>>>(
        ab, proj_w, proj_b, x, x1, C_, H_ * TOPK_);

    // 5. LN2
    ln_kernel<<<M_, 256>>>(x1, n2g, n2b, h);

    // 6. hid = gelu(h @ fc1_w^T + fc1_b)   [M, 3072]
    gemm_mma<true, true, false><<<dim3(HID_ / 128, M_ / 128), 256>>>(
        h, fc1_w, fc1_b, nullptr, hid, HID_, C_);

    // 7. out = x1 + hid @ fc2_w^T + fc2_b  [M, 768]
    gemm_mma<true, false, true><<<dim3(C_ / 128, M_ / 128), 256>>>(
        hid, fc2_w, fc2_b, x1, out, C_, HID_);
}

// round 4
// speedup vs baseline: 3.1705x; 1.2304x over previous
#include <cuda_runtime.h>
#include <math.h>
#include <stdint.h>

#define B_   64
#define N_   196
#define C_   768
#define H_   12
#define HD_  64
#define TOPK_ 16
#define HID_ 3072
#define M_   (B_ * N_)          // 12544
#define SCALE_ 0.125f
#define EPS_ 1e-5f

// ---------------- scratch (device globals) ----------------
__device__ float g_h  [(size_t)M_ * C_];
__device__ float g_qk [(size_t)M_ * 2 * C_];
__device__ float g_a  [(size_t)M_ * H_ * TOPK_];
__device__ float g_x1 [(size_t)M_ * C_];
__device__ float g_hid[(size_t)M_ * HID_];

// ---------------- helpers ----------------
__device__ __forceinline__ void cp_async16(void* smem, const void* gmem) {
    uint32_t s = (uint32_t)__cvta_generic_to_shared(smem);
    asm volatile("cp.async.cg.shared.global [%0], [%1], 16;\n" :: "r"(s), "l"(gmem));
}
__device__ __forceinline__ void cp_commit() { asm volatile("cp.async.commit_group;\n"); }
template <int Np>
__device__ __forceinline__ void cp_wait() { asm volatile("cp.async.wait_group %0;\n" :: "n"(Np) : "memory"); }
__device__ __forceinline__ void ldsm4(uint32_t& r0, uint32_t& r1, uint32_t& r2, uint32_t& r3,
                                      uint32_t addr) {
    asm volatile("ldmatrix.sync.aligned.m8n8.x4.shared.b16 {%0,%1,%2,%3}, [%4];\n"
                 : "=r"(r0), "=r"(r1), "=r"(r2), "=r"(r3) : "r"(addr));
}

// ---------------- LayerNorm ----------------
__global__ void ln_kernel(const float* __restrict__ x, const float* __restrict__ g,
                          const float* __restrict__ b, float* __restrict__ out) {
    int row = blockIdx.x;
    const float* xr = x + (size_t)row * C_;
    int tid = threadIdx.x, lane = tid & 31, warp = tid >> 5;

    float s = 0.f, s2 = 0.f;
    for (int i = tid; i < C_; i += blockDim.x) { float v = xr[i]; s += v; s2 += v * v; }
    #pragma unroll
    for (int o = 16; o > 0; o >>= 1) {
        s  += __shfl_xor_sync(0xffffffffu, s,  o);
        s2 += __shfl_xor_sync(0xffffffffu, s2, o);
    }
    __shared__ float shs[8], shs2[8], sh_mu, sh_inv;
    if (lane == 0) { shs[warp] = s; shs2[warp] = s2; }
    __syncthreads();
    if (tid == 0) {
        float ts = 0.f, ts2 = 0.f;
        #pragma unroll
        for (int w = 0; w < 8; w++) { ts += shs[w]; ts2 += shs2[w]; }
        float mu = ts / C_;
        sh_mu = mu; sh_inv = rsqrtf(ts2 / C_ - mu * mu + EPS_);
    }
    __syncthreads();
    float mu = sh_mu, inv = sh_inv;
    for (int i = tid; i < C_; i += blockDim.x)
        out[(size_t)row * C_ + i] = (xr[i] - mu) * inv * g[i] + b[i];
}

// ---------------- TF32 mma.sync GEMM v2 ----------------
// out[M,Nout] = A[M,K] @ W[Nout,K]^T (+bias)(gelu)(+res)
// BM=BN=128, BK=32, 3-stage cp.async, SW128-swizzled smem, ldmatrix frag loads.
#define STG_B 32768               // 2 * 128 rows * 128 B
#define NSTG  3
#define SMEM_SZ (NSTG * STG_B)

template <bool BIAS, bool GELU, bool RES>
__global__ __launch_bounds__(256, 2) void gemm_mma(
        const float* __restrict__ A, const float* __restrict__ W,
        const float* __restrict__ bias, const float* __restrict__ res,
        float* __restrict__ out, int Nout, int K) {
    extern __shared__ char smem[];
    uint32_t sb = (uint32_t)__cvta_generic_to_shared(smem);

    int tid = threadIdx.x;
    int lane = tid & 31, wid = tid >> 5;
    int wr = wid >> 2, wc = wid & 3;
    int g = lane >> 2, t = lane & 3;
    int grp = lane >> 3, l7 = lane & 7;
    int bm = blockIdx.y * 128, bn = blockIdx.x * 128;

    const float* Ablk = A + (size_t)bm * K;
    const float* Wblk = W + (size_t)bn * K;

    float c[4][4][4];
    #pragma unroll
    for (int i = 0; i < 4; i++)
        #pragma unroll
        for (int j = 0; j < 4; j++)
            #pragma unroll
            for (int r = 0; r < 4; r++) c[i][j][r] = 0.f;

    // per-stage loader: A rows then W rows; 2048 16B tasks / 256 threads = 8
    auto load_stage = [&](int slot, int k0) {
        char* sbase = smem + slot * STG_B;
        #pragma unroll
        for (int i = 0; i < 8; i++) {
            int idx = tid + i * 256;
            int isB = idx >> 10;
            int rem = idx & 1023;
            int row = rem >> 3, seg = rem & 7;
            const float* src = (isB ? Wblk : Ablk) + (size_t)row * K + k0 + seg * 4;
            char* dst = sbase + isB * 16384 + row * 128 + (((seg ^ (row & 7))) << 4);
            cp_async16(dst, src);
        }
        cp_commit();
    };

    int NK = K / 32;
    load_stage(0, 0);
    load_stage(1, 32);

    // precomputed frag-load row/seg offsets
    int rowoffA = (grp & 1) * 8, segoffA = grp >> 1;
    int rowoffB = (grp >> 1) * 8, segoffB = grp & 1;

    for (int kc = 0; kc < NK; kc++) {
        int slot = kc % NSTG;
        cp_wait<1>();
        __syncthreads();

        uint32_t sA = sb + slot * STG_B;
        uint32_t sB = sA + 16384;

        #pragma unroll
        for (int j = 0; j < 4; j++) {         // 4 k8 steps within BK=32
            uint32_t a[4][4], b[4][2];
            #pragma unroll
            for (int ti = 0; ti < 4; ti++) {
                int row = wr * 64 + ti * 16 + rowoffA + l7;
                uint32_t addr = sA + (row << 7) + (((2 * j + segoffA) ^ (row & 7)) << 4);
                ldsm4(a[ti][0], a[ti][1], a[ti][2], a[ti][3], addr);
            }
            #pragma unroll
            for (int tp = 0; tp < 2; tp++) {
                int row = wc * 32 + tp * 16 + rowoffB + l7;
                uint32_t addr = sB + (row << 7) + (((2 * j + segoffB) ^ (row & 7)) << 4);
                uint32_t r0, r1, r2, r3;
                ldsm4(r0, r1, r2, r3, addr);
                b[2 * tp][0] = r0; b[2 * tp][1] = r1;
                b[2 * tp + 1][0] = r2; b[2 * tp + 1][1] = r3;
            }
            #pragma unroll
            for (int ti = 0; ti < 4; ti++)
                #pragma unroll
                for (int tj = 0; tj < 4; tj++) {
                    asm volatile(
                        "mma.sync.aligned.m16n8k8.row.col.f32.tf32.tf32.f32 "
                        "{%0,%1,%2,%3}, {%4,%5,%6,%7}, {%8,%9}, {%0,%1,%2,%3};\n"
                        : "+f"(c[ti][tj][0]), "+f"(c[ti][tj][1]),
                          "+f"(c[ti][tj][2]), "+f"(c[ti][tj][3])
                        : "r"(a[ti][0]), "r"(a[ti][1]), "r"(a[ti][2]), "r"(a[ti][3]),
                          "r"(b[tj][0]), "r"(b[tj][1]));
                }
        }
        __syncthreads();
        if (kc + 2 < NK) load_stage((kc + 2) % NSTG, (kc + 2) * 32);
        else cp_commit();   // keep group count aligned for cp_wait<1>
    }

    // epilogue
    #pragma unroll
    for (int ti = 0; ti < 4; ti++) {
        int r0 = bm + wr * 64 + ti * 16 + g;
        #pragma unroll
        for (int tj = 0; tj < 4; tj++) {
            int cn = bn + wc * 32 + tj * 8 + t * 2;
            float v[4] = {c[ti][tj][0], c[ti][tj][1], c[ti][tj][2], c[ti][tj][3]};
            if (BIAS) {
                float b0 = bias[cn], b1 = bias[cn + 1];
                v[0] += b0; v[1] += b1; v[2] += b0; v[3] += b1;
            }
            if (GELU) {
                #pragma unroll
                for (int q = 0; q < 4; q++)
                    v[q] = 0.5f * v[q] * (1.0f + erff(v[q] * 0.70710678118654752f));
            }
            if (RES) {
                float2 r0v = *(const float2*)&res[(size_t)r0 * Nout + cn];
                float2 r1v = *(const float2*)&res[(size_t)(r0 + 8) * Nout + cn];
                v[0] += r0v.x; v[1] += r0v.y; v[2] += r1v.x; v[3] += r1v.y;
            }
            *(float2*)&out[(size_t)r0 * Nout + cn]       = make_float2(v[0], v[1]);
            *(float2*)&out[(size_t)(r0 + 8) * Nout + cn] = make_float2(v[2], v[3]);
        }
    }
}

// ---------------- fused attention: scores + top-16 + softmax ----------------
__global__ void attn_topk_kernel(const float* __restrict__ qk, float* __restrict__ a) {
    int bh = blockIdx.x;
    int b = bh / H_, h = bh % H_;
    extern __shared__ float sm[];
    float* Qs = sm;
    float* Ks = sm + N_ * HD_;

    int tid = threadIdx.x, lane = tid & 31, warp = tid >> 5;
    int nwarp = blockDim.x >> 5;

    const float* base = qk + (size_t)b * N_ * (2 * C_);
    for (int e = tid; e < N_ * HD_; e += blockDim.x) {
        int n = e / HD_, d = e % HD_;
        Qs[n * HD_ + d] = base[(size_t)n * (2 * C_) + h * HD_ + d] * SCALE_;
        Ks[n * 65 + d]  = base[(size_t)n * (2 * C_) + C_ + h * HD_ + d];
    }
    __syncthreads();

    for (int i = warp; i < N_; i += nwarp) {
        int jj[7];
        float sloc[7];
        #pragma unroll
        for (int t2 = 0; t2 < 7; t2++) {
            int j = lane + 32 * t2;
            jj[t2] = (j < N_) ? j : 0;
            sloc[t2] = 0.f;
        }
        const float* qrow = Qs + i * HD_;
        #pragma unroll 8
        for (int d = 0; d < HD_; d++) {
            float qv = qrow[d];
            #pragma unroll
            for (int t2 = 0; t2 < 7; t2++) sloc[t2] += qv * Ks[jj[t2] * 65 + d];
        }
        #pragma unroll
        for (int t2 = 0; t2 < 7; t2++)
            if (lane + 32 * t2 >= N_) sloc[t2] = -INFINITY;

        float top[16];
        #pragma unroll
        for (int sel = 0; sel < TOPK_; sel++) {
            float m = sloc[0]; int tl = 0;
            #pragma unroll
            for (int t2 = 1; t2 < 7; t2++)
                if (sloc[t2] > m) { m = sloc[t2]; tl = t2; }
            int key = (lane << 3) | tl;
            #pragma unroll
            for (int o = 16; o > 0; o >>= 1) {
                float om = __shfl_xor_sync(0xffffffffu, m, o);
                int ok   = __shfl_xor_sync(0xffffffffu, key, o);
                if (om > m || (om == m && ok < key)) { m = om; key = ok; }
            }
            top[sel] = m;
            if (lane == (key >> 3)) sloc[key & 7] = -INFINITY;
        }

        float ssum = 0.f;
        #pragma unroll
        for (int t2 = 0; t2 < TOPK_; t2++) ssum += expf(top[t2] - top[0]);
        if (lane < TOPK_) {
            float val = expf(top[lane] - top[0]) / ssum;
            a[((size_t)(b * N_ + i)) * (H_ * TOPK_) + h * TOPK_ + lane] = val;
        }
    }
}

// ---------------- launch ----------------
extern "C" void kernel_launch(void* const* d_in, const int* in_sizes, int n_in,
                              void* d_out, int out_size) {
    const float* x      = (const float*)d_in[0];
    const float* n1g    = (const float*)d_in[1];
    const float* n1b    = (const float*)d_in[2];
    const float* qk_w   = (const float*)d_in[3];
    const float* proj_w = (const float*)d_in[4];
    const float* proj_b = (const float*)d_in[5];
    const float* n2g    = (const float*)d_in[6];
    const float* n2b    = (const float*)d_in[7];
    const float* fc1_w  = (const float*)d_in[8];
    const float* fc1_b  = (const float*)d_in[9];
    const float* fc2_w  = (const float*)d_in[10];
    const float* fc2_b  = (const float*)d_in[11];
    float* out = (float*)d_out;

    float *h, *qkb, *ab, *x1, *hid;
    cudaGetSymbolAddress((void**)&h,   g_h);
    cudaGetSymbolAddress((void**)&qkb, g_qk);
    cudaGetSymbolAddress((void**)&ab,  g_a);
    cudaGetSymbolAddress((void**)&x1,  g_x1);
    cudaGetSymbolAddress((void**)&hid, g_hid);

    cudaFuncSetAttribute((const void*)gemm_mma<false,false,false>, cudaFuncAttributeMaxDynamicSharedMemorySize, SMEM_SZ);
    cudaFuncSetAttribute((const void*)gemm_mma<true,false,true>,   cudaFuncAttributeMaxDynamicSharedMemorySize, SMEM_SZ);
    cudaFuncSetAttribute((const void*)gemm_mma<true,true,false>,   cudaFuncAttributeMaxDynamicSharedMemorySize, SMEM_SZ);

    // 1. LN1
    ln_kernel<<<M_, 256>>>(x, n1g, n1b, h);

    // 2. qk = h @ qk_w^T   [M, 1536], K=768
    gemm_mma<false, false, false><<<dim3((2 * C_) / 128, M_ / 128), 256, SMEM_SZ>>>(
        h, qk_w, nullptr, nullptr, qkb, 2 * C_, C_);

    // 3. attention -> a [M, 192]
    int smem = (N_ * HD_ + N_ * 65) * (int)sizeof(float);
    cudaFuncSetAttribute(attn_topk_kernel, cudaFuncAttributeMaxDynamicSharedMemorySize, smem);
    attn_topk_kernel<<<B_ * H_, 256, smem>>>(qkb, ab);

    // 4. x1 = x + a @ proj_w^T + proj_b   [M, 768], K=192
    gemm_mma<true, false, true><<<dim3(C_ / 128, M_ / 128), 256, SMEM_SZ>>>(
        ab, proj_w, proj_b, x, x1, C_, H_ * TOPK_);

    // 5. LN2
    ln_kernel<<<M_, 256>>>(x1, n2g, n2b, h);

    // 6. hid = gelu(h @ fc1_w^T + fc1_b)   [M, 3072], K=768
    gemm_mma<true, true, false><<<dim3(HID_ / 128, M_ / 128), 256, SMEM_SZ>>>(
        h, fc1_w, fc1_b, nullptr, hid, HID_, C_);

    // 7. out = x1 + hid @ fc2_w^T + fc2_b  [M, 768], K=3072
    gemm_mma<true, false, true><<<dim3(C_ / 128, M_ / 128), 256, SMEM_SZ>>>(
        hid, fc2_w, fc2_b, x1, out, C_, HID_);
}

// round 5
// speedup vs baseline: 3.3162x; 1.0460x over previous
#include <cuda_runtime.h>
#include <math.h>
#include <stdint.h>

#define B_   64
#define N_   196
#define C_   768
#define H_   12
#define HD_  64
#define TOPK_ 16
#define HID_ 3072
#define M_   (B_ * N_)          // 12544
#define SCALE_ 0.125f
#define EPS_ 1e-5f

// ---------------- scratch (device globals) ----------------
__device__ float g_h  [(size_t)M_ * C_];
__device__ float g_qk [(size_t)M_ * 2 * C_];
__device__ float g_a  [(size_t)M_ * H_ * TOPK_];
__device__ float g_x1 [(size_t)M_ * C_];
__device__ float g_hid[(size_t)M_ * HID_];

// ---------------- helpers ----------------
__device__ __forceinline__ void cp_async16(void* smem, const void* gmem) {
    uint32_t s = (uint32_t)__cvta_generic_to_shared(smem);
    asm volatile("cp.async.cg.shared.global [%0], [%1], 16;\n" :: "r"(s), "l"(gmem));
}
__device__ __forceinline__ void cp_commit() { asm volatile("cp.async.commit_group;\n"); }
template <int Np>
__device__ __forceinline__ void cp_wait() { asm volatile("cp.async.wait_group %0;\n" :: "n"(Np) : "memory"); }
__device__ __forceinline__ void ldsm4(uint32_t& r0, uint32_t& r1, uint32_t& r2, uint32_t& r3,
                                      uint32_t addr) {
    asm volatile("ldmatrix.sync.aligned.m8n8.x4.shared.b16 {%0,%1,%2,%3}, [%4];\n"
                 : "=r"(r0), "=r"(r1), "=r"(r2), "=r"(r3) : "r"(addr));
}

// ---------------- LayerNorm ----------------
__global__ void ln_kernel(const float* __restrict__ x, const float* __restrict__ g,
                          const float* __restrict__ b, float* __restrict__ out) {
    int row = blockIdx.x;
    const float* xr = x + (size_t)row * C_;
    int tid = threadIdx.x, lane = tid & 31, warp = tid >> 5;

    float s = 0.f, s2 = 0.f;
    for (int i = tid; i < C_; i += blockDim.x) { float v = xr[i]; s += v; s2 += v * v; }
    #pragma unroll
    for (int o = 16; o > 0; o >>= 1) {
        s  += __shfl_xor_sync(0xffffffffu, s,  o);
        s2 += __shfl_xor_sync(0xffffffffu, s2, o);
    }
    __shared__ float shs[8], shs2[8], sh_mu, sh_inv;
    if (lane == 0) { shs[warp] = s; shs2[warp] = s2; }
    __syncthreads();
    if (tid == 0) {
        float ts = 0.f, ts2 = 0.f;
        #pragma unroll
        for (int w = 0; w < 8; w++) { ts += shs[w]; ts2 += shs2[w]; }
        float mu = ts / C_;
        sh_mu = mu; sh_inv = rsqrtf(ts2 / C_ - mu * mu + EPS_);
    }
    __syncthreads();
    float mu = sh_mu, inv = sh_inv;
    for (int i = tid; i < C_; i += blockDim.x)
        out[(size_t)row * C_ + i] = (xr[i] - mu) * inv * g[i] + b[i];
}

// ---------------- TF32 mma.sync GEMM v3 ----------------
// out[M,Nout] = A[M,K] @ W[Nout,K]^T (+bias)(gelu)(+res)
// BM=BN=128, BK=32. 128 threads = 4 warps (2x2), warp tile 64x64.
// 3-stage cp.async, SW128-swizzled smem, ldmatrix, single barrier per iter.
#define STG_B 32768               // (128+128) rows * 128 B
#define NSTG  3
#define SMEM_SZ (NSTG * STG_B)

template <bool BIAS, bool GELU, bool RES>
__global__ __launch_bounds__(128, 2) void gemm_mma(
        const float* __restrict__ A, const float* __restrict__ W,
        const float* __restrict__ bias, const float* __restrict__ res,
        float* __restrict__ out, int Nout, int K) {
    extern __shared__ char smem[];
    uint32_t sb = (uint32_t)__cvta_generic_to_shared(smem);

    int tid = threadIdx.x;
    int lane = tid & 31, wid = tid >> 5;
    int wr = wid >> 1, wc = wid & 1;          // 2x2 warp grid
    int g = lane >> 2, t = lane & 3;
    int grp = lane >> 3, l7 = lane & 7;
    int bm = blockIdx.y * 128, bn = blockIdx.x * 128;

    const float* Ablk = A + (size_t)bm * K;
    const float* Wblk = W + (size_t)bn * K;

    float c[4][8][4];
    #pragma unroll
    for (int i = 0; i < 4; i++)
        #pragma unroll
        for (int j = 0; j < 8; j++)
            #pragma unroll
            for (int r = 0; r < 4; r++) c[i][j][r] = 0.f;

    // loader: 2048 16B tasks / 128 threads = 16; seg & swizzle col constant per thread
    int lrow0 = tid >> 3;         // 0..15
    int lseg  = tid & 7;
    uint32_t lcol = (uint32_t)((lseg ^ (lrow0 & 7)) << 4);
    auto load_stage = [&](int slot, int k0) {
        char* sbase = smem + slot * STG_B;
        #pragma unroll
        for (int i = 0; i < 16; i++) {
            int row = lrow0 + (i & 7) * 16;
            int isB = i >> 3;
            const float* src = (isB ? Wblk : Ablk) + (size_t)row * K + k0 + lseg * 4;
            char* dst = sbase + isB * 16384 + row * 128 + lcol;
            cp_async16(dst, src);
        }
        cp_commit();
    };

    int NK = K / 32;
    load_stage(0, 0);
    load_stage(1, 32);

    int rowoffA = (grp & 1) * 8, segoffA = grp >> 1;
    int rowoffB = (grp >> 1) * 8, segoffB = grp & 1;

    for (int kc = 0; kc < NK; kc++) {
        int slot = kc % NSTG;
        cp_wait<1>();
        __syncthreads();

        if (kc + 2 < NK) load_stage((kc + 2) % NSTG, (kc + 2) * 32);
        else cp_commit();

        uint32_t sA = sb + slot * STG_B;
        uint32_t sB = sA + 16384;

        #pragma unroll
        for (int j = 0; j < 4; j++) {         // 4 k8 steps in BK=32
            uint32_t a[4][4], b[8][2];
            #pragma unroll
            for (int ti = 0; ti < 4; ti++) {
                int row = wr * 64 + ti * 16 + rowoffA + l7;
                uint32_t addr = sA + (row << 7) + (((2 * j + segoffA) ^ (row & 7)) << 4);
                ldsm4(a[ti][0], a[ti][1], a[ti][2], a[ti][3], addr);
            }
            #pragma unroll
            for (int tp = 0; tp < 4; tp++) {
                int row = wc * 64 + tp * 16 + rowoffB + l7;
                uint32_t addr = sB + (row << 7) + (((2 * j + segoffB) ^ (row & 7)) << 4);
                uint32_t r0, r1, r2, r3;
                ldsm4(r0, r1, r2, r3, addr);
                b[2 * tp][0] = r0; b[2 * tp][1] = r1;
                b[2 * tp + 1][0] = r2; b[2 * tp + 1][1] = r3;
            }
            #pragma unroll
            for (int ti = 0; ti < 4; ti++)
                #pragma unroll
                for (int tj = 0; tj < 8; tj++) {
                    asm volatile(
                        "mma.sync.aligned.m16n8k8.row.col.f32.tf32.tf32.f32 "
                        "{%0,%1,%2,%3}, {%4,%5,%6,%7}, {%8,%9}, {%0,%1,%2,%3};\n"
                        : "+f"(c[ti][tj][0]), "+f"(c[ti][tj][1]),
                          "+f"(c[ti][tj][2]), "+f"(c[ti][tj][3])
                        : "r"(a[ti][0]), "r"(a[ti][1]), "r"(a[ti][2]), "r"(a[ti][3]),
                          "r"(b[tj][0]), "r"(b[tj][1]));
                }
        }
    }

    // epilogue
    #pragma unroll
    for (int ti = 0; ti < 4; ti++) {
        int r0 = bm + wr * 64 + ti * 16 + g;
        #pragma unroll
        for (int tj = 0; tj < 8; tj++) {
            int cn = bn + wc * 64 + tj * 8 + t * 2;
            float v[4] = {c[ti][tj][0], c[ti][tj][1], c[ti][tj][2], c[ti][tj][3]};
            if (BIAS) {
                float b0 = bias[cn], b1 = bias[cn + 1];
                v[0] += b0; v[1] += b1; v[2] += b0; v[3] += b1;
            }
            if (GELU) {
                #pragma unroll
                for (int q = 0; q < 4; q++)
                    v[q] = 0.5f * v[q] * (1.0f + erff(v[q] * 0.70710678118654752f));
            }
            if (RES) {
                float2 r0v = *(const float2*)&res[(size_t)r0 * Nout + cn];
                float2 r1v = *(const float2*)&res[(size_t)(r0 + 8) * Nout + cn];
                v[0] += r0v.x; v[1] += r0v.y; v[2] += r1v.x; v[3] += r1v.y;
            }
            *(float2*)&out[(size_t)r0 * Nout + cn]       = make_float2(v[0], v[1]);
            *(float2*)&out[(size_t)(r0 + 8) * Nout + cn] = make_float2(v[2], v[3]);
        }
    }
}

// ---------------- fused attention: scores + top-16 + softmax ----------------
__global__ void attn_topk_kernel(const float* __restrict__ qk, float* __restrict__ a) {
    int bh = blockIdx.x;
    int b = bh / H_, h = bh % H_;
    extern __shared__ float sm[];
    float* Qs = sm;
    float* Ks = sm + N_ * HD_;

    int tid = threadIdx.x, lane = tid & 31, warp = tid >> 5;
    int nwarp = blockDim.x >> 5;

    const float* base = qk + (size_t)b * N_ * (2 * C_);
    for (int e = tid; e < N_ * HD_; e += blockDim.x) {
        int n = e / HD_, d = e % HD_;
        Qs[n * HD_ + d] = base[(size_t)n * (2 * C_) + h * HD_ + d] * SCALE_;
        Ks[n * 65 + d]  = base[(size_t)n * (2 * C_) + C_ + h * HD_ + d];
    }
    __syncthreads();

    for (int i = warp; i < N_; i += nwarp) {
        int jj[7];
        float sloc[7];
        #pragma unroll
        for (int t2 = 0; t2 < 7; t2++) {
            int j = lane + 32 * t2;
            jj[t2] = (j < N_) ? j : 0;
            sloc[t2] = 0.f;
        }
        const float* qrow = Qs + i * HD_;
        #pragma unroll 8
        for (int d = 0; d < HD_; d++) {
            float qv = qrow[d];
            #pragma unroll
            for (int t2 = 0; t2 < 7; t2++) sloc[t2] += qv * Ks[jj[t2] * 65 + d];
        }
        #pragma unroll
        for (int t2 = 0; t2 < 7; t2++)
            if (lane + 32 * t2 >= N_) sloc[t2] = -INFINITY;

        float top[16];
        #pragma unroll
        for (int sel = 0; sel < TOPK_; sel++) {
            float m = sloc[0]; int tl = 0;
            #pragma unroll
            for (int t2 = 1; t2 < 7; t2++)
                if (sloc[t2] > m) { m = sloc[t2]; tl = t2; }
            int key = (lane << 3) | tl;
            #pragma unroll
            for (int o = 16; o > 0; o >>= 1) {
                float om = __shfl_xor_sync(0xffffffffu, m, o);
                int ok   = __shfl_xor_sync(0xffffffffu, key, o);
                if (om > m || (om == m && ok < key)) { m = om; key = ok; }
            }
            top[sel] = m;
            if (lane == (key >> 3)) sloc[key & 7] = -INFINITY;
        }

        float ssum = 0.f;
        #pragma unroll
        for (int t2 = 0; t2 < TOPK_; t2++) ssum += expf(top[t2] - top[0]);
        if (lane < TOPK_) {
            float val = expf(top[lane] - top[0]) / ssum;
            a[((size_t)(b * N_ + i)) * (H_ * TOPK_) + h * TOPK_ + lane] = val;
        }
    }
}

// ---------------- launch ----------------
extern "C" void kernel_launch(void* const* d_in, const int* in_sizes, int n_in,
                              void* d_out, int out_size) {
    const float* x      = (const float*)d_in[0];
    const float* n1g    = (const float*)d_in[1];
    const float* n1b    = (const float*)d_in[2];
    const float* qk_w   = (const float*)d_in[3];
    const float* proj_w = (const float*)d_in[4];
    const float* proj_b = (const float*)d_in[5];
    const float* n2g    = (const float*)d_in[6];
    const float* n2b    = (const float*)d_in[7];
    const float* fc1_w  = (const float*)d_in[8];
    const float* fc1_b  = (const float*)d_in[9];
    const float* fc2_w  = (const float*)d_in[10];
    const float* fc2_b  = (const float*)d_in[11];
    float* out = (float*)d_out;

    float *h, *qkb, *ab, *x1, *hid;
    cudaGetSymbolAddress((void**)&h,   g_h);
    cudaGetSymbolAddress((void**)&qkb, g_qk);
    cudaGetSymbolAddress((void**)&ab,  g_a);
    cudaGetSymbolAddress((void**)&x1,  g_x1);
    cudaGetSymbolAddress((void**)&hid, g_hid);

    cudaFuncSetAttribute((const void*)gemm_mma<false,false,false>, cudaFuncAttributeMaxDynamicSharedMemorySize, SMEM_SZ);
    cudaFuncSetAttribute((const void*)gemm_mma<true,false,true>,   cudaFuncAttributeMaxDynamicSharedMemorySize, SMEM_SZ);
    cudaFuncSetAttribute((const void*)gemm_mma<true,true,false>,   cudaFuncAttributeMaxDynamicSharedMemorySize, SMEM_SZ);

    // 1. LN1
    ln_kernel<<<M_, 256>>>(x, n1g, n1b, h);

    // 2. qk = h @ qk_w^T   [M, 1536], K=768
    gemm_mma<false, false, false><<<dim3((2 * C_) / 128, M_ / 128), 128, SMEM_SZ>>>(
        h, qk_w, nullptr, nullptr, qkb, 2 * C_, C_);

    // 3. attention -> a [M, 192]
    int smem = (N_ * HD_ + N_ * 65) * (int)sizeof(float);
    cudaFuncSetAttribute(attn_topk_kernel, cudaFuncAttributeMaxDynamicSharedMemorySize, smem);
    attn_topk_kernel<<<B_ * H_, 256, smem>>>(qkb, ab);

    // 4. x1 = x + a @ proj_w^T + proj_b   [M, 768], K=192
    gemm_mma<true, false, true><<<dim3(C_ / 128, M_ / 128), 128, SMEM_SZ>>>(
        ab, proj_w, proj_b, x, x1, C_, H_ * TOPK_);

    // 5. LN2
    ln_kernel<<<M_, 256>>>(x1, n2g, n2b, h);

    // 6. hid = gelu(h @ fc1_w^T + fc1_b)   [M, 3072], K=768
    gemm_mma<true, true, false><<<dim3(HID_ / 128, M_ / 128), 128, SMEM_SZ>>>(
        h, fc1_w, fc1_b, nullptr, hid, HID_, C_);

    // 7. out = x1 + hid @ fc2_w^T + fc2_b  [M, 768], K=3072
    gemm_mma<true, false, true><<<dim3(C_ / 128, M_ / 128), 128, SMEM_SZ>>>(
        hid, fc2_w, fc2_b, x1, out, C_, HID_);
}

// round 7
// speedup vs baseline: 4.1410x; 1.2487x over previous
#include <cuda_runtime.h>
#include <cuda_fp16.h>
#include <math.h>
#include <stdint.h>

#define B_   64
#define N_   196
#define C_   768
#define H_   12
#define HD_  64
#define TOPK_ 16
#define HID_ 3072
#define M_   (B_ * N_)          // 12544
#define SCALE_ 0.125f
#define EPS_ 1e-5f

// ---------------- scratch (device globals) ----------------
__device__ __half g_h_h  [(size_t)M_ * C_];
__device__ float  g_qk   [(size_t)M_ * 2 * C_];
__device__ __half g_a_h  [(size_t)M_ * H_ * TOPK_];
__device__ float  g_x1   [(size_t)M_ * C_];
__device__ __half g_hid_h[(size_t)M_ * HID_];
// fp16 weights
__device__ __half g_qkw_h[(size_t)2 * C_ * C_];
__device__ __half g_pw_h [(size_t)C_ * H_ * TOPK_];
__device__ __half g_f1w_h[(size_t)HID_ * C_];
__device__ __half g_f2w_h[(size_t)C_ * HID_];

// ---------------- helpers ----------------
__device__ __forceinline__ void cp_async16(void* smem, const void* gmem) {
    uint32_t s = (uint32_t)__cvta_generic_to_shared(smem);
    asm volatile("cp.async.cg.shared.global [%0], [%1], 16;\n" :: "r"(s), "l"(gmem));
}
__device__ __forceinline__ void cp_commit() { asm volatile("cp.async.commit_group;\n"); }
template <int Np>
__device__ __forceinline__ void cp_wait() { asm volatile("cp.async.wait_group %0;\n" :: "n"(Np) : "memory"); }
__device__ __forceinline__ void ldsm4(uint32_t& r0, uint32_t& r1, uint32_t& r2, uint32_t& r3,
                                      uint32_t addr) {
    asm volatile("ldmatrix.sync.aligned.m8n8.x4.shared.b16 {%0,%1,%2,%3}, [%4];\n"
                 : "=r"(r0), "=r"(r1), "=r"(r2), "=r"(r3) : "r"(addr));
}

// ---------------- weight fp32 -> fp16 ----------------
__global__ void cvt_kernel(const float* __restrict__ src, __half* __restrict__ dst, int n) {
    int i = (blockIdx.x * 256 + threadIdx.x) * 2;
    if (i < n) {
        float2 v = *(const float2*)&src[i];
        *(__half2*)&dst[i] = __floats2half2_rn(v.x, v.y);
    }
}

// ---------------- LayerNorm -> fp16 ----------------
__global__ void ln_kernel(const float* __restrict__ x, const float* __restrict__ g,
                          const float* __restrict__ b, __half* __restrict__ out) {
    int row = blockIdx.x;
    const float* xr = x + (size_t)row * C_;
    int tid = threadIdx.x, lane = tid & 31, warp = tid >> 5;

    float s = 0.f, s2 = 0.f;
    for (int i = tid; i < C_; i += blockDim.x) { float v = xr[i]; s += v; s2 += v * v; }
    #pragma unroll
    for (int o = 16; o > 0; o >>= 1) {
        s  += __shfl_xor_sync(0xffffffffu, s,  o);
        s2 += __shfl_xor_sync(0xffffffffu, s2, o);
    }
    __shared__ float shs[8], shs2[8], sh_mu, sh_inv;
    if (lane == 0) { shs[warp] = s; shs2[warp] = s2; }
    __syncthreads();
    if (tid == 0) {
        float ts = 0.f, ts2 = 0.f;
        #pragma unroll
        for (int w = 0; w < 8; w++) { ts += shs[w]; ts2 += shs2[w]; }
        float mu = ts / C_;
        sh_mu = mu; sh_inv = rsqrtf(ts2 / C_ - mu * mu + EPS_);
    }
    __syncthreads();
    float mu = sh_mu, inv = sh_inv;
    for (int i = tid; i < C_; i += blockDim.x) {
        float v = (xr[i] - mu) * inv * g[i] + b[i];
        out[(size_t)row * C_ + i] = __float2half(v);
    }
}

// ---------------- FP16 mma.sync GEMM ----------------
// out[M,Nout] = A[M,K] @ W[Nout,K]^T (+bias)(gelu)(+res), fp32 accumulate.
// BM=BN=128, BK=64 (128B fp16 rows). 128 threads = 4 warps (2x2), warp tile 64x64.
// 3-stage cp.async, SW128 swizzle, ldmatrix.x4, m16n8k16.
#define STG_B 32768               // (128+128) rows * 128 B
#define NSTG  3
#define SMEM_SZ (NSTG * STG_B)

template <bool BIAS, bool GELU, bool RES, bool OUTH>
__global__ __launch_bounds__(128, 2) void gemm_h(
        const __half* __restrict__ A, const __half* __restrict__ W,
        const float* __restrict__ bias, const float* __restrict__ res,
        float* __restrict__ outf, __half* __restrict__ outh, int Nout, int K) {
    extern __shared__ char smem[];
    uint32_t sb = (uint32_t)__cvta_generic_to_shared(smem);

    int tid = threadIdx.x;
    int lane = tid & 31, wid = tid >> 5;
    int wr = wid >> 1, wc = wid & 1;
    int g = lane >> 2, t = lane & 3;
    int grp = lane >> 3, l7 = lane & 7;
    int bm = blockIdx.y * 128, bn = blockIdx.x * 128;

    const __half* Ablk = A + (size_t)bm * K;
    const __half* Wblk = W + (size_t)bn * K;

    float c[4][8][4];
    #pragma unroll
    for (int i = 0; i < 4; i++)
        #pragma unroll
        for (int j = 0; j < 8; j++)
            #pragma unroll
            for (int r = 0; r < 4; r++) c[i][j][r] = 0.f;

    // loader: 2048 16B tasks / 128 threads = 16
    int lrow0 = tid >> 3;
    int lseg  = tid & 7;
    uint32_t lcol = (uint32_t)((lseg ^ (lrow0 & 7)) << 4);
    auto load_stage = [&](int slot, int k0) {
        char* sbase = smem + slot * STG_B;
        #pragma unroll
        for (int i = 0; i < 16; i++) {
            int row = lrow0 + (i & 7) * 16;
            int isB = i >> 3;
            const __half* src = (isB ? Wblk : Ablk) + (size_t)row * K + k0 + lseg * 8;
            char* dst = sbase + isB * 16384 + row * 128 + lcol;
            cp_async16(dst, src);
        }
        cp_commit();
    };

    int NK = K / 64;
    load_stage(0, 0);
    load_stage(1, 64);

    int rowoffA = (grp & 1) * 8, segoffA = grp >> 1;
    int rowoffB = (grp >> 1) * 8, segoffB = grp & 1;

    for (int kc = 0; kc < NK; kc++) {
        int slot = kc % NSTG;
        cp_wait<1>();
        __syncthreads();

        if (kc + 2 < NK) load_stage((kc + 2) % NSTG, (kc + 2) * 64);
        else cp_commit();

        uint32_t sA = sb + slot * STG_B;
        uint32_t sB = sA + 16384;

        #pragma unroll
        for (int j = 0; j < 4; j++) {         // 4 k16-steps in BK=64
            uint32_t a[4][4], b[8][2];
            #pragma unroll
            for (int ti = 0; ti < 4; ti++) {
                int row = wr * 64 + ti * 16 + rowoffA + l7;
                uint32_t addr = sA + (row << 7) + (((2 * j + segoffA) ^ (row & 7)) << 4);
                ldsm4(a[ti][0], a[ti][1], a[ti][2], a[ti][3], addr);
            }
            #pragma unroll
            for (int tp = 0; tp < 4; tp++) {
                int row = wc * 64 + tp * 16 + rowoffB + l7;
                uint32_t addr = sB + (row << 7) + (((2 * j + segoffB) ^ (row & 7)) << 4);
                uint32_t r0, r1, r2, r3;
                ldsm4(r0, r1, r2, r3, addr);
                b[2 * tp][0] = r0; b[2 * tp][1] = r1;
                b[2 * tp + 1][0] = r2; b[2 * tp + 1][1] = r3;
            }
            #pragma unroll
            for (int ti = 0; ti < 4; ti++)
                #pragma unroll
                for (int tj = 0; tj < 8; tj++) {
                    asm volatile(
                        "mma.sync.aligned.m16n8k16.row.col.f32.f16.f16.f32 "
                        "{%0,%1,%2,%3}, {%4,%5,%6,%7}, {%8,%9}, {%0,%1,%2,%3};\n"
                        : "+f"(c[ti][tj][0]), "+f"(c[ti][tj][1]),
                          "+f"(c[ti][tj][2]), "+f"(c[ti][tj][3])
                        : "r"(a[ti][0]), "r"(a[ti][1]), "r"(a[ti][2]), "r"(a[ti][3]),
                          "r"(b[tj][0]), "r"(b[tj][1]));
                }
        }
    }

    // epilogue
    #pragma unroll
    for (int ti = 0; ti < 4; ti++) {
        int r0 = bm + wr * 64 + ti * 16 + g;
        #pragma unroll
        for (int tj = 0; tj < 8; tj++) {
            int cn = bn + wc * 64 + tj * 8 + t * 2;
            float v[4] = {c[ti][tj][0], c[ti][tj][1], c[ti][tj][2], c[ti][tj][3]};
            if (BIAS) {
                float b0 = bias[cn], b1 = bias[cn + 1];
                v[0] += b0; v[1] += b1; v[2] += b0; v[3] += b1;
            }
            if (GELU) {
                #pragma unroll
                for (int q = 0; q < 4; q++)
                    v[q] = 0.5f * v[q] * (1.0f + erff(v[q] * 0.70710678118654752f));
            }
            if (RES) {
                float2 r0v = *(const float2*)&res[(size_t)r0 * Nout + cn];
                float2 r1v = *(const float2*)&res[(size_t)(r0 + 8) * Nout + cn];
                v[0] += r0v.x; v[1] += r0v.y; v[2] += r1v.x; v[3] += r1v.y;
            }
            if (OUTH) {
                *(__half2*)&outh[(size_t)r0 * Nout + cn]       = __floats2half2_rn(v[0], v[1]);
                *(__half2*)&outh[(size_t)(r0 + 8) * Nout + cn] = __floats2half2_rn(v[2], v[3]);
            } else {
                *(float2*)&outf[(size_t)r0 * Nout + cn]       = make_float2(v[0], v[1]);
                *(float2*)&outf[(size_t)(r0 + 8) * Nout + cn] = make_float2(v[2], v[3]);
            }
        }
    }
}

// ---------------- fused attention: scores + top-16 + softmax -> fp16 ----------------
__global__ void attn_topk_kernel(const float* __restrict__ qk, __half* __restrict__ a) {
    int bh = blockIdx.x;
    int b = bh / H_, h = bh % H_;
    extern __shared__ float sm[];
    float* Qs = sm;
    float* Ks = sm + N_ * HD_;

    int tid = threadIdx.x, lane = tid & 31, warp = tid >> 5;
    int nwarp = blockDim.x >> 5;

    const float* base = qk + (size_t)b * N_ * (2 * C_);
    for (int e = tid; e < N_ * HD_; e += blockDim.x) {
        int n = e / HD_, d = e % HD_;
        Qs[n * HD_ + d] = base[(size_t)n * (2 * C_) + h * HD_ + d] * SCALE_;
        Ks[n * 65 + d]  = base[(size_t)n * (2 * C_) + C_ + h * HD_ + d];
    }
    __syncthreads();

    for (int i = warp; i < N_; i += nwarp) {
        int jj[7];
        float sloc[7];
        #pragma unroll
        for (int t2 = 0; t2 < 7; t2++) {
            int j = lane + 32 * t2;
            jj[t2] = (j < N_) ? j : 0;
            sloc[t2] = 0.f;
        }
        const float* qrow = Qs + i * HD_;
        #pragma unroll 8
        for (int d = 0; d < HD_; d++) {
            float qv = qrow[d];
            #pragma unroll
            for (int t2 = 0; t2 < 7; t2++) sloc[t2] += qv * Ks[jj[t2] * 65 + d];
        }
        #pragma unroll
        for (int t2 = 0; t2 < 7; t2++)
            if (lane + 32 * t2 >= N_) sloc[t2] = -INFINITY;

        float top[16];
        #pragma unroll
        for (int sel = 0; sel < TOPK_; sel++) {
            float m = sloc[0]; int tl = 0;
            #pragma unroll
            for (int t2 = 1; t2 < 7; t2++)
                if (sloc[t2] > m) { m = sloc[t2]; tl = t2; }
            int key = (lane << 3) | tl;
            #pragma unroll
            for (int o = 16; o > 0; o >>= 1) {
                float om = __shfl_xor_sync(0xffffffffu, m, o);
                int ok   = __shfl_xor_sync(0xffffffffu, key, o);
                if (om > m || (om == m && ok < key)) { m = om; key = ok; }
            }
            top[sel] = m;
            if (lane == (key >> 3)) sloc[key & 7] = -INFINITY;
        }

        float ssum = 0.f;
        #pragma unroll
        for (int t2 = 0; t2 < TOPK_; t2++) ssum += expf(top[t2] - top[0]);
        if (lane < TOPK_) {
            float val = expf(top[lane] - top[0]) / ssum;
            a[((size_t)(b * N_ + i)) * (H_ * TOPK_) + h * TOPK_ + lane] = __float2half(val);
        }
    }
}

// ---------------- launch ----------------
extern "C" void kernel_launch(void* const* d_in, const int* in_sizes, int n_in,
                              void* d_out, int out_size) {
    const float* x      = (const float*)d_in[0];
    const float* n1g    = (const float*)d_in[1];
    const float* n1b    = (const float*)d_in[2];
    const float* qk_w   = (const float*)d_in[3];
    const float* proj_w = (const float*)d_in[4];
    const float* proj_b = (const float*)d_in[5];
    const float* n2g    = (const float*)d_in[6];
    const float* n2b    = (const float*)d_in[7];
    const float* fc1_w  = (const float*)d_in[8];
    const float* fc1_b  = (const float*)d_in[9];
    const float* fc2_w  = (const float*)d_in[10];
    const float* fc2_b  = (const float*)d_in[11];
    float* out = (float*)d_out;

    __half *h_h, *a_h, *hid_h, *qkw_h, *pw_h, *f1w_h, *f2w_h;
    float *qkb, *x1;
    cudaGetSymbolAddress((void**)&h_h,   g_h_h);
    cudaGetSymbolAddress((void**)&qkb,   g_qk);
    cudaGetSymbolAddress((void**)&a_h,   g_a_h);
    cudaGetSymbolAddress((void**)&x1,    g_x1);
    cudaGetSymbolAddress((void**)&hid_h, g_hid_h);
    cudaGetSymbolAddress((void**)&qkw_h, g_qkw_h);
    cudaGetSymbolAddress((void**)&pw_h,  g_pw_h);
    cudaGetSymbolAddress((void**)&f1w_h, g_f1w_h);
    cudaGetSymbolAddress((void**)&f2w_h, g_f2w_h);

    cudaFuncSetAttribute((const void*)gemm_h<false,false,false,false>, cudaFuncAttributeMaxDynamicSharedMemorySize, SMEM_SZ);
    cudaFuncSetAttribute((const void*)gemm_h<true,false,true,false>,   cudaFuncAttributeMaxDynamicSharedMemorySize, SMEM_SZ);
    cudaFuncSetAttribute((const void*)gemm_h<true,true,false,true>,    cudaFuncAttributeMaxDynamicSharedMemorySize, SMEM_SZ);

    // weight conversions (fp32 -> fp16)
    {
        int n;
        n = 2 * C_ * C_;     cvt_kernel<<<(n / 2 + 255) / 256, 256>>>(qk_w,   qkw_h, n);
        n = C_ * H_ * TOPK_; cvt_kernel<<<(n / 2 + 255) / 256, 256>>>(proj_w, pw_h,  n);
        n = HID_ * C_;       cvt_kernel<<<(n / 2 + 255) / 256, 256>>>(fc1_w,  f1w_h, n);
        n = C_ * HID_;       cvt_kernel<<<(n / 2 + 255) / 256, 256>>>(fc2_w,  f2w_h, n);
    }

    // 1. LN1 -> fp16
    ln_kernel<<<M_, 256>>>(x, n1g, n1b, h_h);

    // 2. qk = h @ qk_w^T   [M, 1536], K=768 (fp32 out)
    gemm_h<false, false, false, false><<<dim3((2 * C_) / 128, M_ / 128), 128, SMEM_SZ>>>(
        h_h, qkw_h, nullptr, nullptr, qkb, nullptr, 2 * C_, C_);

    // 3. attention -> a fp16 [M, 192]
    int smem = (N_ * HD_ + N_ * 65) * (int)sizeof(float);
    cudaFuncSetAttribute(attn_topk_kernel, cudaFuncAttributeMaxDynamicSharedMemorySize, smem);
    attn_topk_kernel<<<B_ * H_, 256, smem>>>(qkb, a_h);

    // 4. x1 = x + a @ proj_w^T + proj_b   [M, 768], K=192
    gemm_h<true, false, true, false><<<dim3(C_ / 128, M_ / 128), 128, SMEM_SZ>>>(
        a_h, pw_h, proj_b, x, x1, nullptr, C_, H_ * TOPK_);

    // 5. LN2 -> fp16
    ln_kernel<<<M_, 256>>>(x1, n2g, n2b, h_h);

    // 6. hid = gelu(h @ fc1_w^T + fc1_b) -> fp16 [M, 3072], K=768
    gemm_h<true, true, false, true><<<dim3(HID_ / 128, M_ / 128), 128, SMEM_SZ>>>(
        h_h, f1w_h, fc1_b, nullptr, nullptr, hid_h, HID_, C_);

    // 7. out = x1 + hid @ fc2_w^T + fc2_b  [M, 768], K=3072
    gemm_h<true, false, true, false><<<dim3(C_ / 128, M_ / 128), 128, SMEM_SZ>>>(
        hid_h, f2w_h, fc2_b, x1, out, nullptr, C_, HID_);
}